// round 7
// baseline (speedup 1.0000x reference)
#include <cuda_runtime.h>

// Problem shape (fixed by the dataset)
constexpr int Bsz = 256;
constexpr int Lsz = 65536;
constexpr int Tc  = 64;           // samples per chunk (per thread)
constexpr int Cc  = Lsz / Tc;     // 1024 chunks per row = threads per block
constexpr int NW  = Cc / 32;      // 32 warps per block

// Paul Kellet pink filter coefficients (scalar constexprs fold fine in device code)
constexpr float A0 = 0.99886f, A1 = 0.99332f, A2 = 0.969f,
                A3 = 0.8665f,  A4 = 0.55f,    A5 = -0.7616f;
constexpr float DIRECT = 0.5362f, OUT_GAIN = 0.11f, B6_GAIN = 0.115926f;
constexpr float OGD = OUT_GAIN * DIRECT;     // coeff on current white
constexpr float OGB = OUT_GAIN * B6_GAIN;    // coeff on previous white

// Flush-to-zero guard: nvcc's constexpr evaluator hard-errors on FP underflow,
// so clamp tiny intermediates to exact 0 (mathematically 0 at fp32 precision).
constexpr double ftz(double x) {
    return (x < 1e-100 && x > -1e-100) ? 0.0 : x;
}
// compile-time pow (double accumulation, binary exponentiation, FTZ-guarded)
constexpr double cdpow(double a, long long n) {
    double r = 1.0, p = a;
    while (n > 0) {
        if (n & 1) r = ftz(r * p);
        p = ftz(p * p);
        n >>= 1;
    }
    return r;
}
constexpr float cpowf(double a, long long n) {
    double r = cdpow(a, n);
    if (r < 1e-37 && r > -1e-37) return 0.0f;
    return (float)r;
}

// Coefficient tables must live in device memory space: plain constexpr arrays
// are host-only symbols without --expt-relaxed-constexpr.
__device__ __constant__ float A_[6] = {A0, A1, A2, A3, A4, A5};
__device__ __constant__ float C_[6] = {0.0555179f, 0.0750759f, 0.153852f,
                                       0.3104856f, 0.5329522f, -0.016898f};

// warp-scan weights  W_[p][j] = A_p^(Tc * 2^j),        j = 0..4 (d=1..16)
// cross-warp weights X_[p][j] = A_p^(Tc * 32 * 2^j),   j = 0..4 (d=1..16, 32 warps)
// per-chunk multiplier M_[p]  = A_p^Tc (float, for per-lane pow)
#define WARR(A) { cpowf(A,(long long)Tc), cpowf(A,(long long)Tc*2), cpowf(A,(long long)Tc*4), \
                  cpowf(A,(long long)Tc*8), cpowf(A,(long long)Tc*16) }
#define XARR(A) { cpowf(A,(long long)Tc*32), cpowf(A,(long long)Tc*64), \
                  cpowf(A,(long long)Tc*128), cpowf(A,(long long)Tc*256), \
                  cpowf(A,(long long)Tc*512) }
__device__ __constant__ float W_[6][5] =
    { WARR(A0), WARR(A1), WARR(A2), WARR(A3), WARR(A4), WARR(A5) };
__device__ __constant__ float X_[6][5] =
    { XARR(A0), XARR(A1), XARR(A2), XARR(A3), XARR(A4), XARR(A5) };
__device__ __constant__ float M_[6] =
    { cpowf(A0,Tc), cpowf(A1,Tc), cpowf(A2,Tc),
      cpowf(A3,Tc), cpowf(A4,Tc), cpowf(A5,Tc) };

// float binary pow, n in [1, 32] (6 bits, fully unrolled — no FP64 on the hot path)
__device__ __forceinline__ float fpow6(float m, int n) {
    float r = 1.f, p = m;
#pragma unroll
    for (int i = 0; i < 6; ++i) { if (n & 1) r *= p; p *= p; n >>= 1; }
    return r;
}

// ---------------------------------------------------------------------------
// One block per row (1024 threads, 2 blocks/SM). Three phases in one kernel:
//   1) per-chunk local pole states (zero init)
//   2) Kogge-Stone scan over chunks -> exact init state per chunk
//   3) re-run chunk from init state, emit pink
// ---------------------------------------------------------------------------
__global__ void __launch_bounds__(Cc, 2) k_pink(const float* __restrict__ white,
                                                float* __restrict__ pink) {
    const int b = blockIdx.x;
    const int k = threadIdx.x;              // chunk index within row
    const int lane = k & 31, wid = k >> 5;

    const size_t off = (size_t)b * Lsz + (size_t)k * Tc;
    const float4* w4 = reinterpret_cast<const float4*>(white + off);

    // ---- Phase 1: local pole states with zero initial condition
    float s[6];
#pragma unroll
    for (int p = 0; p < 6; ++p) s[p] = 0.f;

#pragma unroll 4
    for (int t = 0; t < Tc / 4; ++t) {
        float4 w = w4[t];
        float xs[4] = {w.x, w.y, w.z, w.w};
#pragma unroll
        for (int i = 0; i < 4; ++i)
#pragma unroll
            for (int p = 0; p < 6; ++p)
                s[p] = fmaf(A_[p], s[p], C_[p] * xs[i]);
    }

    // ---- Phase 2: inclusive scan I(k) = sum_{j<=k} M^(k-j) local(j)
    float v[6];
#pragma unroll
    for (int p = 0; p < 6; ++p) v[p] = s[p];

    // warp-level Kogge-Stone (d = 1,2,4,8,16)
#pragma unroll
    for (int j = 0; j < 5; ++j) {
        const int d = 1 << j;
        float u[6];
#pragma unroll
        for (int p = 0; p < 6; ++p) u[p] = __shfl_up_sync(0xffffffffu, v[p], d);
        if (lane >= d)
#pragma unroll
            for (int p = 0; p < 6; ++p) v[p] = fmaf(W_[p][j], u[p], v[p]);
    }

    __shared__ float tot[NW][6];
    __shared__ float pre[NW][6];
    if (lane == 31)
#pragma unroll
        for (int p = 0; p < 6; ++p) tot[wid][p] = v[p];
    __syncthreads();

    // warp 0 scans the 32 warp totals with weight X = M^32 (d = 1,2,4,8,16)
    if (wid == 0) {
        float t[6];
#pragma unroll
        for (int p = 0; p < 6; ++p) t[p] = tot[lane][p];
#pragma unroll
        for (int j = 0; j < 5; ++j) {
            const int d = 1 << j;
            float u[6];
#pragma unroll
            for (int p = 0; p < 6; ++p) u[p] = __shfl_up_sync(0xffffffffu, t[p], d);
            if (lane >= d)
#pragma unroll
                for (int p = 0; p < 6; ++p) t[p] = fmaf(X_[p][j], u[p], t[p]);
        }
        // exclusive prefix E_w = inclusive(w-1), E_0 = 0
#pragma unroll
        for (int p = 0; p < 6; ++p) {
            float e = __shfl_up_sync(0xffffffffu, t[p], 1);
            if (lane == 0) e = 0.f;
            pre[lane][p] = e;
        }
    }
    __syncthreads();

    // combine: I(k) = v + M^(lane+1) * E_w
    float pw[6], lf[6];
#pragma unroll
    for (int p = 0; p < 6; ++p) pw[p] = pre[wid][p];
#pragma unroll
    for (int p = 0; p < 6; ++p) lf[p] = fpow6(M_[p], lane + 1);
#pragma unroll
    for (int p = 0; p < 6; ++p) v[p] = fmaf(lf[p], pw[p], v[p]);

    // init state for this chunk = I(k-1); lane 0 takes E_w (k=0 -> E_0 = 0)
    float ini[6];
#pragma unroll
    for (int p = 0; p < 6; ++p) {
        float u = __shfl_up_sync(0xffffffffu, v[p], 1);
        ini[p] = (lane == 0) ? pw[p] : u;
    }

    // ---- Phase 3: re-run chunk from exact init, emit pink
    float xprev = (k > 0) ? white[off - 1] : 0.f;
#pragma unroll
    for (int p = 0; p < 6; ++p) s[p] = ini[p];
    float4* o4 = reinterpret_cast<float4*>(pink + off);

#pragma unroll 2
    for (int t = 0; t < Tc / 4; ++t) {
        float4 w = w4[t];
        float xs[4] = {w.x, w.y, w.z, w.w};
        float ys[4];
#pragma unroll
        for (int i = 0; i < 4; ++i) {
#pragma unroll
            for (int p = 0; p < 6; ++p)
                s[p] = fmaf(A_[p], s[p], C_[p] * xs[i]);
            float sum = ((s[0] + s[1]) + (s[2] + s[3])) + (s[4] + s[5]);
            ys[i] = fmaf(OUT_GAIN, sum, fmaf(OGD, xs[i], OGB * xprev));
            xprev = xs[i];
        }
        float4 o;
        o.x = ys[0]; o.y = ys[1]; o.z = ys[2]; o.w = ys[3];
        o4[t] = o;
    }
}

// ---------------------------------------------------------------------------
extern "C" void kernel_launch(void* const* d_in, const int* in_sizes, int n_in,
                              void* d_out, int out_size) {
    const float* white = (const float*)d_in[0];
    float* pink = (float*)d_out;
    (void)in_sizes; (void)n_in; (void)out_size;

    k_pink<<<Bsz, Cc>>>(white, pink);
}

// round 9
// speedup vs baseline: 1.0727x; 1.0727x over previous
#include <cuda_runtime.h>

// Problem shape (fixed by the dataset)
constexpr int Bsz = 256;
constexpr int Lsz = 65536;
constexpr int Tc  = 128;          // samples per chunk (per thread)
constexpr int Cc  = Lsz / Tc;     // 512 chunks per row = threads per block
constexpr int NW  = Cc / 32;      // 16 warps per block

// Paul Kellet pink filter coefficients
constexpr float A0 = 0.99886f, A1 = 0.99332f, A2 = 0.969f,
                A3 = 0.8665f,  A4 = 0.55f,    A5 = -0.7616f;
constexpr float C0c = 0.0555179f, C1c = 0.0750759f, C2c = 0.153852f,
                C3c = 0.3104856f, C4c = 0.5329522f, C5c = -0.016898f;
constexpr float DIRECT = 0.5362f, OUT_GAIN = 0.11f, B6_GAIN = 0.115926f;
constexpr float OGD = OUT_GAIN * DIRECT;
constexpr float OGB = OUT_GAIN * B6_GAIN;
// output-dot coefficients on the SCALED states r_p = s_p / C_p
constexpr float D0 = OUT_GAIN * C0c, D1 = OUT_GAIN * C1c, D2 = OUT_GAIN * C2c,
                D3 = OUT_GAIN * C3c, D4 = OUT_GAIN * C4c, D5 = OUT_GAIN * C5c;

// Flush-to-zero guard: nvcc's constexpr evaluator hard-errors on FP underflow.
constexpr double ftz(double x) {
    return (x < 1e-100 && x > -1e-100) ? 0.0 : x;
}
constexpr double cdpow(double a, long long n) {
    double r = 1.0, p = a;
    while (n > 0) {
        if (n & 1) r = ftz(r * p);
        p = ftz(p * p);
        n >>= 1;
    }
    return r;
}
constexpr float cpowf(double a, long long n) {
    double r = cdpow(a, n);
    if (r < 1e-37 && r > -1e-37) return 0.0f;
    return (float)r;
}

// Scan weight tables (compile-time indices only; device memory space required
// since plain constexpr arrays are host-only without --expt-relaxed-constexpr).
#define WARR(A) { cpowf(A,(long long)Tc), cpowf(A,(long long)Tc*2), cpowf(A,(long long)Tc*4), \
                  cpowf(A,(long long)Tc*8), cpowf(A,(long long)Tc*16) }
#define XARR(A) { cpowf(A,(long long)Tc*32), cpowf(A,(long long)Tc*64), \
                  cpowf(A,(long long)Tc*128), cpowf(A,(long long)Tc*256) }
__device__ __constant__ float W_[6][5] =
    { WARR(A0), WARR(A1), WARR(A2), WARR(A3), WARR(A4), WARR(A5) };
__device__ __constant__ float X_[6][4] =
    { XARR(A0), XARR(A1), XARR(A2), XARR(A3), XARR(A4), XARR(A5) };
__device__ __constant__ float M_[6] =
    { cpowf(A0,Tc), cpowf(A1,Tc), cpowf(A2,Tc),
      cpowf(A3,Tc), cpowf(A4,Tc), cpowf(A5,Tc) };

// float binary pow, n in [1, 32]
__device__ __forceinline__ float fpow6(float m, int n) {
    float r = 1.f, p = m;
#pragma unroll
    for (int i = 0; i < 6; ++i) { if (n & 1) r *= p; p *= p; n >>= 1; }
    return r;
}

// Scaled-state pole update: r_p = A_p * r_p + x  (literal A -> FFMA-imm, rt=1)
#define POLES_STEP(x)                      \
    {                                      \
        r0 = fmaf(A0, r0, (x));            \
        r1 = fmaf(A1, r1, (x));            \
        r2 = fmaf(A2, r2, (x));            \
        r3 = fmaf(A3, r3, (x));            \
        r4 = fmaf(A4, r4, (x));            \
        r5 = fmaf(A5, r5, (x));            \
    }

// ---------------------------------------------------------------------------
// One block per row (512 threads). Three phases:
//   1) per-chunk local scaled pole states (zero init)   — 6 FFMA/sample
//   2) Kogge-Stone scan over chunks -> init state per chunk
//   3) re-run chunk from init, emit pink                — 14 ops/sample
// ---------------------------------------------------------------------------
__global__ void __launch_bounds__(Cc) k_pink(const float* __restrict__ white,
                                             float* __restrict__ pink) {
    const int b = blockIdx.x;
    const int k = threadIdx.x;              // chunk index within row
    const int lane = k & 31, wid = k >> 5;

    const size_t off = (size_t)b * Lsz + (size_t)k * Tc;
    const float4* w4 = reinterpret_cast<const float4*>(white + off);

    // ---- Phase 1: local scaled pole states, zero initial condition
    float r0 = 0.f, r1 = 0.f, r2 = 0.f, r3 = 0.f, r4 = 0.f, r5 = 0.f;

#pragma unroll 4
    for (int t = 0; t < Tc / 4; ++t) {
        float4 w = w4[t];
        POLES_STEP(w.x) POLES_STEP(w.y) POLES_STEP(w.z) POLES_STEP(w.w)
    }

    // ---- Phase 2: inclusive scan I(k) = sum_{j<=k} M^(k-j) local(j)
    float v[6] = {r0, r1, r2, r3, r4, r5};

    // warp-level Kogge-Stone (d = 1,2,4,8,16)
#pragma unroll
    for (int j = 0; j < 5; ++j) {
        const int d = 1 << j;
        float u[6];
#pragma unroll
        for (int p = 0; p < 6; ++p) u[p] = __shfl_up_sync(0xffffffffu, v[p], d);
        if (lane >= d)
#pragma unroll
            for (int p = 0; p < 6; ++p) v[p] = fmaf(W_[p][j], u[p], v[p]);
    }

    __shared__ float tot[NW][6];
    __shared__ float pre[NW][6];
    if (lane == 31)
#pragma unroll
        for (int p = 0; p < 6; ++p) tot[wid][p] = v[p];
    __syncthreads();

    // warp 0 scans the 16 warp totals (d = 1,2,4,8)
    if (wid == 0) {
        float t[6];
#pragma unroll
        for (int p = 0; p < 6; ++p) t[p] = (lane < NW) ? tot[lane][p] : 0.f;
#pragma unroll
        for (int j = 0; j < 4; ++j) {
            const int d = 1 << j;
            float u[6];
#pragma unroll
            for (int p = 0; p < 6; ++p) u[p] = __shfl_up_sync(0xffffffffu, t[p], d);
            if (lane >= d)
#pragma unroll
                for (int p = 0; p < 6; ++p) t[p] = fmaf(X_[p][j], u[p], t[p]);
        }
        // exclusive prefix E_w = inclusive(w-1), E_0 = 0
#pragma unroll
        for (int p = 0; p < 6; ++p) {
            float e = __shfl_up_sync(0xffffffffu, t[p], 1);
            if (lane == 0) e = 0.f;
            if (lane < NW) pre[lane][p] = e;
        }
    }
    __syncthreads();

    // combine: I(k) = v + M^(lane+1) * E_w
    float pw[6];
#pragma unroll
    for (int p = 0; p < 6; ++p) pw[p] = pre[wid][p];
#pragma unroll
    for (int p = 0; p < 6; ++p) {
        float lf = fpow6(M_[p], lane + 1);
        v[p] = fmaf(lf, pw[p], v[p]);
    }

    // init state for this chunk = I(k-1); lane 0 takes E_w
    float ini[6];
#pragma unroll
    for (int p = 0; p < 6; ++p) {
        float u = __shfl_up_sync(0xffffffffu, v[p], 1);
        ini[p] = (lane == 0) ? pw[p] : u;
    }

    // ---- Phase 3: re-run chunk from exact init, emit pink
    float xprev = (k > 0) ? white[off - 1] : 0.f;
    r0 = ini[0]; r1 = ini[1]; r2 = ini[2];
    r3 = ini[3]; r4 = ini[4]; r5 = ini[5];
    float4* o4 = reinterpret_cast<float4*>(pink + off);

#pragma unroll 2
    for (int t = 0; t < Tc / 4; ++t) {
        float4 w = w4[t];
        float xs[4] = {w.x, w.y, w.z, w.w};
        float ys[4];
#pragma unroll
        for (int i = 0; i < 4; ++i) {
            const float x = xs[i];
            POLES_STEP(x)
            float acc = fmaf(OGD, x, OGB * xprev);
            acc = fmaf(D0, r0, acc);
            acc = fmaf(D1, r1, acc);
            acc = fmaf(D2, r2, acc);
            acc = fmaf(D3, r3, acc);
            acc = fmaf(D4, r4, acc);
            ys[i] = fmaf(D5, r5, acc);
            xprev = x;
        }
        float4 o;
        o.x = ys[0]; o.y = ys[1]; o.z = ys[2]; o.w = ys[3];
        o4[t] = o;
    }
}

// ---------------------------------------------------------------------------
extern "C" void kernel_launch(void* const* d_in, const int* in_sizes, int n_in,
                              void* d_out, int out_size) {
    const float* white = (const float*)d_in[0];
    float* pink = (float*)d_out;
    (void)in_sizes; (void)n_in; (void)out_size;

    k_pink<<<Bsz, Cc>>>(white, pink);
}